// round 3
// baseline (speedup 1.0000x reference)
#include <cuda_runtime.h>

// Patch2Im gather, residue-specialized warps.
// out[bc,h,w] = mean over valid (i,j): xp[bc,i,j,ph,pw], hp=h+3=i+3*ph, wp=w+3=j+3*pw.
// Block = (h, bc); 3 warps, warp r handles outputs with w % 3 == r.
// Lane l, iter k -> q = 32k+l, w = 3q+r: per-tap lane addresses are contiguous
// in pw => fully coalesced 128B warp loads. Tap counts uniform per warp/block.

#define BATCH 4
#define CH 64
#define KP 7
#define NHW 85
#define OH 253
#define OW 253
#define PS (NHW * NHW)        // 7225

__global__ void __launch_bounds__(96)
patch2im_kernel(const float* __restrict__ xp, float* __restrict__ out)
{
    int h    = blockIdx.x;                 // 0..252
    int bc   = blockIdx.y;                 // 0..255
    int r    = threadIdx.x >> 5;           // warp id = residue class 0..2
    int lane = threadIdx.x & 31;

    int hp = h + 3;                        // 3..255
    int qh = hp / 3;                       // 1..85
    int rh = hp % 3;
    int nrow = (rh == 0) ? 3 : 2;          // uniform across block

    // Row taps: i = rh + 3a, ph = qh - a. Edge-invalid taps get weight 0
    // and a safe clamped address.
    float wr[3];
    int   roff[3];
#pragma unroll
    for (int a = 0; a < 3; ++a) {
        int ph = qh - a;
        bool v = (a < nrow) && (ph >= 0) && (ph < NHW);
        wr[a] = v ? 1.0f : 0.0f;
        int phc = min(max(ph, 0), NHW - 1);
        int ic  = (a < nrow) ? (rh + 3 * a) : rh;
        roff[a] = ic * (KP * PS) + phc * NHW;
    }
    float nrowv = wr[0] + wr[1] + wr[2];   // valid row count (edge-adjusted)

    int ncol = (r == 0) ? 3 : 2;           // uniform across warp

    const float* base = xp + (size_t)bc * (KP * KP * PS);
    float* orow = out + ((size_t)bc * OH + h) * OW;

    for (int k = 0; k < 3; ++k) {
        int q = k * 32 + lane;             // quotient index
        int w = 3 * q + r;
        if (w >= OW) continue;             // only trims tail of k==2

        float sum  = 0.0f;
        float ncolv = 0.0f;
        for (int m = 0; m < ncol; ++m) {   // uniform trip count per warp
            int j  = r + 3 * m;
            int pw = q + 1 - m;
            bool v = (pw >= 0) && (pw < NHW);
            float wcv = v ? 1.0f : 0.0f;
            int pwc = v ? pw : 0;
            const float* p = base + j * PS + pwc;
            float cs = 0.0f;
            for (int a = 0; a < nrow; ++a) // uniform trip count per block
                cs += wr[a] * __ldg(p + roff[a]);
            sum   += wcv * cs;
            ncolv += wcv;
        }
        orow[w] = __fdividef(sum, nrowv * ncolv);
    }
}

extern "C" void kernel_launch(void* const* d_in, const int* in_sizes, int n_in,
                              void* d_out, int out_size)
{
    const float* xp = (const float*)d_in[0];
    float* outp = (float*)d_out;
    dim3 grid(OH, BATCH * CH);             // (253, 256)
    patch2im_kernel<<<grid, 96>>>(xp, outp);
}

// round 4
// speedup vs baseline: 1.1980x; 1.1980x over previous
#include <cuda_runtime.h>

// Patch2Im gather, residue-major lane mapping + specialized unrolled bodies.
// out[bc,h,w] = mean over valid (i,j) of xp[bc,i,j,ph,pw],
//   h+3 = i + 3*ph, w+3 = j + 3*pw, i,j in [0,7), ph,pw in [0,85).
// Valid i's: i = rh + 3a (a < nrow, nrow = rh==0 ? 3 : 2); same for j with r.
// Lanes grouped by residue r = w%3 -> per-tap warp loads are contiguous in pw.

#define PS 7225               // 85*85
#define CST (7 * PS)          // stride of i index
#define OH 253
#define OW 253

__global__ void __launch_bounds__(256)
patch2im_kernel(const float* __restrict__ xp, float* __restrict__ out)
{
    int s = threadIdx.x;
    if (s >= 253) return;
    int h  = blockIdx.x;              // 0..252
    int bc = blockIdx.y;              // 0..255

    // residue-major output mapping: [r=0: q=0..84][r=1: q=0..83][r=2: q=0..83]
    int r, q;
    if (s < 85)       { r = 0; q = s; }
    else if (s < 169) { r = 1; q = s - 85; }
    else              { r = 2; q = s - 169; }

    int hp = h + 3;                   // 3..255
    int qh = hp / 3;                  // 1..85
    int rh = hp % 3;

    const float* base = xp + (size_t)bc * (49 * PS);
    float* op = out + ((size_t)bc * OH + h) * OW + (3 * q + r);

    if (rh == 0) {                    // rows i = 0,3,6 ; ph = qh, qh-1, qh-2
        float wr0 = (qh <= 84) ? 1.f : 0.f;      // qh==85 -> ph=85 invalid
        float wr2 = (qh >= 2)  ? 1.f : 0.f;      // qh==1  -> ph=-1 invalid
        int ro0 = 0 * CST + ((qh <= 84) ? qh : 0) * 85;
        int ro1 = 3 * CST + (qh - 1) * 85;
        int ro2 = 6 * CST + ((qh >= 2) ? (qh - 2) : 0) * 85;
        float inr = (wr0 + wr2 == 2.f) ? (1.f / 3.f) : 0.5f;

        if (r == 0) {                 // cols j = 0,3,6 ; pw = q+1, q, q-1
            float wc0 = (q <= 83) ? 1.f : 0.f;
            float wc2 = (q >= 1)  ? 1.f : 0.f;
            int c0 = 0 * PS + ((q <= 83) ? q + 1 : 0);
            int c1 = 3 * PS + q;
            int c2 = 6 * PS + ((q >= 1) ? q - 1 : 0);
            float s0 = wr0 * __ldg(base + ro0 + c0) + __ldg(base + ro1 + c0) + wr2 * __ldg(base + ro2 + c0);
            float s1 = wr0 * __ldg(base + ro0 + c1) + __ldg(base + ro1 + c1) + wr2 * __ldg(base + ro2 + c1);
            float s2 = wr0 * __ldg(base + ro0 + c2) + __ldg(base + ro1 + c2) + wr2 * __ldg(base + ro2 + c2);
            float inc = (wc0 + wc2 == 2.f) ? (1.f / 3.f) : 0.5f;
            *op = (wc0 * s0 + s1 + wc2 * s2) * (inr * inc);
        } else {                      // cols j = r, r+3 ; pw = q+1, q (always valid)
            int c0 = r * PS + (q + 1);
            int c1 = (r + 3) * PS + q;
            float s0 = wr0 * __ldg(base + ro0 + c0) + __ldg(base + ro1 + c0) + wr2 * __ldg(base + ro2 + c0);
            float s1 = wr0 * __ldg(base + ro0 + c1) + __ldg(base + ro1 + c1) + wr2 * __ldg(base + ro2 + c1);
            *op = (s0 + s1) * (inr * 0.5f);
        }
    } else {                          // rows i = rh, rh+3 ; ph = qh, qh-1 (always valid)
        int ro0 = rh * CST + qh * 85;
        int ro1 = (rh + 3) * CST + (qh - 1) * 85;

        if (r == 0) {
            float wc0 = (q <= 83) ? 1.f : 0.f;
            float wc2 = (q >= 1)  ? 1.f : 0.f;
            int c0 = 0 * PS + ((q <= 83) ? q + 1 : 0);
            int c1 = 3 * PS + q;
            int c2 = 6 * PS + ((q >= 1) ? q - 1 : 0);
            float s0 = __ldg(base + ro0 + c0) + __ldg(base + ro1 + c0);
            float s1 = __ldg(base + ro0 + c1) + __ldg(base + ro1 + c1);
            float s2 = __ldg(base + ro0 + c2) + __ldg(base + ro1 + c2);
            float inc = (wc0 + wc2 == 2.f) ? (1.f / 3.f) : 0.5f;
            *op = (wc0 * s0 + s1 + wc2 * s2) * (0.5f * inc);
        } else {                      // pure interior 2x2: count always 4
            int c0 = r * PS + (q + 1);
            int c1 = (r + 3) * PS + q;
            float v = __ldg(base + ro0 + c0) + __ldg(base + ro1 + c0)
                    + __ldg(base + ro0 + c1) + __ldg(base + ro1 + c1);
            *op = v * 0.25f;
        }
    }
}

extern "C" void kernel_launch(void* const* d_in, const int* in_sizes, int n_in,
                              void* d_out, int out_size)
{
    const float* xp = (const float*)d_in[0];
    float* outp = (float*)d_out;
    dim3 grid(OH, 256);               // (h, b*C)
    patch2im_kernel<<<grid, 256>>>(xp, outp);
}

// round 5
// speedup vs baseline: 1.3307x; 1.1108x over previous
#include <cuda_runtime.h>

// Patch2Im gather, residue-major lanes + specialized bodies + 4-way channel
// batching. Each thread computes the same (h,w) output for 4 channels
// bc, bc+64, bc+128, bc+192 — identical offsets/validity, 4x the MLP.

#define PS 7225               // 85*85
#define CST (7 * PS)          // stride of i index
#define CHS (49 * PS)         // channel stride (per bc)
#define OH 253
#define OW 253
#define OCH (OH * OW)         // 64009

__global__ void __launch_bounds__(256)
patch2im_kernel(const float* __restrict__ xp, float* __restrict__ out)
{
    int s = threadIdx.x;
    if (s >= 253) return;
    int h   = blockIdx.x;             // 0..252
    int bc0 = blockIdx.y;             // 0..63 ; streams bc0 + 64k

    // residue-major output mapping: [r=0: q=0..84][r=1: q=0..83][r=2: q=0..83]
    int r, q;
    if (s < 85)       { r = 0; q = s; }
    else if (s < 169) { r = 1; q = s - 85; }
    else              { r = 2; q = s - 169; }

    int hp = h + 3;                   // 3..255
    int qh = hp / 3;                  // 1..85
    int rh = hp % 3;

    const float* base0 = xp + (size_t)bc0 * CHS;
    float* op0 = out + (size_t)bc0 * OCH + (size_t)h * OW + (3 * q + r);

    if (rh == 0) {                    // rows i = 0,3,6 ; ph = qh, qh-1, qh-2
        float wr0 = (qh <= 84) ? 1.f : 0.f;
        float wr2 = (qh >= 2)  ? 1.f : 0.f;
        int ro0 = 0 * CST + ((qh <= 84) ? qh : 0) * 85;
        int ro1 = 3 * CST + (qh - 1) * 85;
        int ro2 = 6 * CST + ((qh >= 2) ? (qh - 2) : 0) * 85;
        float inr = (wr0 + wr2 == 2.f) ? (1.f / 3.f) : 0.5f;

        if (r == 0) {                 // cols j = 0,3,6 ; pw = q+1, q, q-1
            float wc0 = (q <= 83) ? 1.f : 0.f;
            float wc2 = (q >= 1)  ? 1.f : 0.f;
            int c0 = 0 * PS + ((q <= 83) ? q + 1 : 0);
            int c1 = 3 * PS + q;
            int c2 = 6 * PS + ((q >= 1) ? q - 1 : 0);
            float scale = inr * ((wc0 + wc2 == 2.f) ? (1.f / 3.f) : 0.5f);
#pragma unroll
            for (int k = 0; k < 4; ++k) {
                const float* b = base0 + (size_t)k * (64 * (size_t)CHS);
                float s0 = wr0 * __ldg(b + ro0 + c0) + __ldg(b + ro1 + c0) + wr2 * __ldg(b + ro2 + c0);
                float s1 = wr0 * __ldg(b + ro0 + c1) + __ldg(b + ro1 + c1) + wr2 * __ldg(b + ro2 + c1);
                float s2 = wr0 * __ldg(b + ro0 + c2) + __ldg(b + ro1 + c2) + wr2 * __ldg(b + ro2 + c2);
                op0[(size_t)k * (64 * (size_t)OCH)] = (wc0 * s0 + s1 + wc2 * s2) * scale;
            }
        } else {                      // cols j = r, r+3 ; pw = q+1, q (always valid)
            int c0 = r * PS + (q + 1);
            int c1 = (r + 3) * PS + q;
            float scale = inr * 0.5f;
#pragma unroll
            for (int k = 0; k < 4; ++k) {
                const float* b = base0 + (size_t)k * (64 * (size_t)CHS);
                float s0 = wr0 * __ldg(b + ro0 + c0) + __ldg(b + ro1 + c0) + wr2 * __ldg(b + ro2 + c0);
                float s1 = wr0 * __ldg(b + ro0 + c1) + __ldg(b + ro1 + c1) + wr2 * __ldg(b + ro2 + c1);
                op0[(size_t)k * (64 * (size_t)OCH)] = (s0 + s1) * scale;
            }
        }
    } else {                          // rows i = rh, rh+3 ; ph = qh, qh-1 (always valid)
        int ro0 = rh * CST + qh * 85;
        int ro1 = (rh + 3) * CST + (qh - 1) * 85;

        if (r == 0) {
            float wc0 = (q <= 83) ? 1.f : 0.f;
            float wc2 = (q >= 1)  ? 1.f : 0.f;
            int c0 = 0 * PS + ((q <= 83) ? q + 1 : 0);
            int c1 = 3 * PS + q;
            int c2 = 6 * PS + ((q >= 1) ? q - 1 : 0);
            float scale = 0.5f * ((wc0 + wc2 == 2.f) ? (1.f / 3.f) : 0.5f);
#pragma unroll
            for (int k = 0; k < 4; ++k) {
                const float* b = base0 + (size_t)k * (64 * (size_t)CHS);
                float s0 = __ldg(b + ro0 + c0) + __ldg(b + ro1 + c0);
                float s1 = __ldg(b + ro0 + c1) + __ldg(b + ro1 + c1);
                float s2 = __ldg(b + ro0 + c2) + __ldg(b + ro1 + c2);
                op0[(size_t)k * (64 * (size_t)OCH)] = (wc0 * s0 + s1 + wc2 * s2) * scale;
            }
        } else {                      // pure interior 2x2: count always 4
            int c0 = r * PS + (q + 1);
            int c1 = (r + 3) * PS + q;
#pragma unroll
            for (int k = 0; k < 4; ++k) {
                const float* b = base0 + (size_t)k * (64 * (size_t)CHS);
                float v = __ldg(b + ro0 + c0) + __ldg(b + ro1 + c0)
                        + __ldg(b + ro0 + c1) + __ldg(b + ro1 + c1);
                op0[(size_t)k * (64 * (size_t)OCH)] = v * 0.25f;
            }
        }
    }
}

extern "C" void kernel_launch(void* const* d_in, const int* in_sizes, int n_in,
                              void* d_out, int out_size)
{
    const float* xp = (const float*)d_in[0];
    float* outp = (float*)d_out;
    dim3 grid(OH, 64);                // (h, bc/4)
    patch2im_kernel<<<grid, 256>>>(xp, outp);
}